// round 16
// baseline (speedup 1.0000x reference)
#include <cuda_runtime.h>
#include <cuda_fp16.h>
#include <cstdint>

#define BB 4
#define CC 256
#define NN 4096
#define HH 4
#define DKK 64

// scratch (allocation-free rule: __device__ globals)
__device__ __half g_xh[(size_t)BB*CC*NN];       // x in f16 [b,c,n]
__device__ __half g_wq[CC*CC], g_wk[CC*CC], g_wv[CC*CC], g_wp[CC*CC];
__device__ __half g_qh[(size_t)BB*HH*NN*DKK];   // [b,h,n,d] (pre-scaled)
__device__ __half g_kh[(size_t)BB*HH*NN*DKK];   // [b,h,n,d]
__device__ __half g_vh[(size_t)BB*HH*NN*DKK];   // [b,h,n,d]
__device__ __half g_ah[(size_t)BB*CC*NN];       // attn out [b,c,n]

// Q pre-scale: (1/sqrt(64)) * log2(e), folded into the Q projection
#define QSCALE 0.1803368801111204f

// ---------------------------------------------------------------------------
// helpers
// ---------------------------------------------------------------------------
__device__ __forceinline__ uint32_t smem_u32(const void* p){
    uint32_t a;
    asm("{ .reg .u64 t; cvta.to.shared.u64 t, %1; cvt.u32.u64 %0, t; }":"=r"(a):"l"(p));
    return a;
}
__device__ __forceinline__ void cp16(uint32_t dst, const void* src){
    asm volatile("cp.async.cg.shared.global [%0],[%1],16;"::"r"(dst),"l"(src):"memory");
}
#define CP_COMMIT() asm volatile("cp.async.commit_group;":::"memory")
#define CP_WAIT0()  asm volatile("cp.async.wait_group 0;":::"memory")
#define CP_WAIT1()  asm volatile("cp.async.wait_group 1;":::"memory")

__device__ __forceinline__ void ldmx4(uint32_t* r, uint32_t addr){
    asm volatile("ldmatrix.sync.aligned.m8n8.x4.shared.b16 {%0,%1,%2,%3}, [%4];"
        : "=r"(r[0]),"=r"(r[1]),"=r"(r[2]),"=r"(r[3]) : "r"(addr));
}
__device__ __forceinline__ void ldmx4t(uint32_t* r, uint32_t addr){
    asm volatile("ldmatrix.sync.aligned.m8n8.x4.trans.shared.b16 {%0,%1,%2,%3}, [%4];"
        : "=r"(r[0]),"=r"(r[1]),"=r"(r[2]),"=r"(r[3]) : "r"(addr));
}
__device__ __forceinline__ void mma_f16(float* c, const uint32_t* a, const uint32_t* b){
    asm volatile("mma.sync.aligned.m16n8k16.row.col.f32.f16.f16.f32 "
        "{%0,%1,%2,%3}, {%4,%5,%6,%7}, {%8,%9}, {%0,%1,%2,%3};"
        : "+f"(c[0]),"+f"(c[1]),"+f"(c[2]),"+f"(c[3])
        : "r"(a[0]),"r"(a[1]),"r"(a[2]),"r"(a[3]), "r"(b[0]),"r"(b[1]));
}
// f16-accumulate variant: C/D are 2 regs of f16x2
__device__ __forceinline__ void mma_f16h(uint32_t* c, const uint32_t* a, const uint32_t* b){
    asm volatile("mma.sync.aligned.m16n8k16.row.col.f16.f16.f16.f16 "
        "{%0,%1}, {%2,%3,%4,%5}, {%6,%7}, {%0,%1};"
        : "+r"(c[0]),"+r"(c[1])
        : "r"(a[0]),"r"(a[1]),"r"(a[2]),"r"(a[3]), "r"(b[0]),"r"(b[1]));
}
__device__ __forceinline__ uint32_t hx2(uint32_t x){
    uint32_t r; asm("ex2.approx.f16x2 %0, %1;" : "=r"(r) : "r"(x)); return r;
}
__device__ __forceinline__ uint32_t hadd2u(uint32_t a, uint32_t b){
    uint32_t r; asm("add.rn.f16x2 %0, %1, %2;" : "=r"(r) : "r"(a), "r"(b)); return r;
}
__device__ __forceinline__ float2 h2f2(uint32_t u){
    __half2 h = *reinterpret_cast<__half2*>(&u);
    return __half22float2(h);
}

// ---------------------------------------------------------------------------
// f32 -> f16 conversion pre-pass
// ---------------------------------------------------------------------------
__global__ __launch_bounds__(256) void cvt_kernel(
    const float4* __restrict__ src, __half* __restrict__ dst, int n4)
{
    int i = blockIdx.x*blockDim.x + threadIdx.x;
    if (i < n4) {
        float4 v = src[i];
        __half2* d2 = (__half2*)(dst + (size_t)i*4);
        d2[0] = __floats2half2_rn(v.x, v.y);
        d2[1] = __floats2half2_rn(v.z, v.w);
    }
}
__global__ __launch_bounds__(256) void cvt_w4_kernel(
    const float4* __restrict__ w0, const float4* __restrict__ w1,
    const float4* __restrict__ w2, const float4* __restrict__ w3,
    __half* __restrict__ d0, __half* __restrict__ d1,
    __half* __restrict__ d2, __half* __restrict__ d3, int n4)
{
    const float4* s; __half* d;
    switch (blockIdx.y) {
        case 0: s = w0; d = d0; break;
        case 1: s = w1; d = d1; break;
        case 2: s = w2; d = d2; break;
        default: s = w3; d = d3; break;
    }
    int i = blockIdx.x*blockDim.x + threadIdx.x;
    if (i < n4) {
        float4 v = s[i];
        __half2* dd = (__half2*)(d + (size_t)i*4);
        dd[0] = __floats2half2_rn(v.x, v.y);
        dd[1] = __floats2half2_rn(v.z, v.w);
    }
}

// ---------------------------------------------------------------------------
// proj_qkv: one CTA loads its x tile ONCE and computes q,k,v for its head.
// out f16 [b][h][n][64]. CTA = 128 n x 64 o. K=256, w staged in 2 halves.
// ---------------------------------------------------------------------------
#define PT_WS   69632u
#define PT_SMEM 103424u

__global__ __launch_bounds__(256,2) void proj_qkv_kernel(
    const __half* __restrict__ xg,
    const __half* __restrict__ wq, const __half* __restrict__ wk,
    const __half* __restrict__ wv,
    const float* __restrict__ bq, const float* __restrict__ bk,
    const float* __restrict__ bv,
    __half* __restrict__ qo, __half* __restrict__ ko, __half* __restrict__ vo)
{
    extern __shared__ __align__(128) char sm[];
    const uint32_t sb = smem_u32(sm);
    const int tid = threadIdx.x, l = tid & 31, w = tid >> 5;
    const int n0 = blockIdx.x*128, h = blockIdx.y, b = blockIdx.z;
    const int o0 = h*64;
    const __half* xb = xg + (size_t)b*CC*NN;

    const __half* wlist[3] = {wq, wk, wv};
    const float*  blist[3] = {bq, bk, bv};
    __half*       olist[3] = {qo, ko, vo};

#pragma unroll
    for (int t = 0; t < 8; t++) {
        int idx = tid + t*256;
        int r = idx >> 4, c = idx & 15;
        cp16(sb + r*272 + c*16, xb + (size_t)r*NN + n0 + c*8);
    }
#pragma unroll
    for (int t = 0; t < 4; t++) {
        int idx = tid + t*256;
        int r = idx >> 4, c = idx & 15;
        cp16(sb + PT_WS + r*528 + c*16, wq + (size_t)(o0 + r)*CC + c*8);
    }
    CP_COMMIT();
#pragma unroll
    for (int t = 0; t < 8; t++) {
        int idx = tid + t*256;
        int r = idx >> 4, c = idx & 15;
        cp16(sb + (128 + r)*272 + c*16, xb + (size_t)(128 + r)*NN + n0 + c*8);
    }
#pragma unroll
    for (int t = 0; t < 4; t++) {
        int idx = tid + t*256;
        int r = idx >> 4, c = idx & 15;
        cp16(sb + PT_WS + r*528 + 256 + c*16, wq + (size_t)(o0 + r)*CC + 128 + c*8);
    }
    CP_COMMIT();

    const int m = l >> 3;
    const int r0 = n0 + w*16 + (l>>2);
    const size_t nb_ = (size_t)(b*HH + h)*NN;

    for (int wi = 0; wi < 3; wi++) {
        float acc[8][4];
#pragma unroll
        for (int i = 0; i < 8; i++)
#pragma unroll
            for (int j = 0; j < 4; j++) acc[i][j] = 0.0f;

        CP_WAIT1();
        __syncthreads();
#pragma unroll
        for (int half = 0; half < 2; half++) {
#pragma unroll
            for (int ks8 = 0; ks8 < 8; ks8++) {
                const int ks = half*8 + ks8;
                uint32_t af[4];
                ldmx4t(af, sb + (uint32_t)(ks*16 + (m>>1)*8 + (l&7))*272
                              + (uint32_t)(w*16 + (m&1)*8)*2);
#pragma unroll
                for (int ob2 = 0; ob2 < 4; ob2++) {
                    uint32_t bf[4];
                    ldmx4(bf, sb + PT_WS + (uint32_t)(ob2*16 + (m>>1)*8 + (l&7))*528
                                  + (uint32_t)(ks*16 + (m&1)*8)*2);
                    mma_f16(acc[ob2*2+0], af, bf+0);
                    mma_f16(acc[ob2*2+1], af, bf+2);
                }
            }
            if (half == 0) { CP_WAIT0(); __syncthreads(); }
        }

        {
            const float scale = (wi == 0) ? QSCALE : 1.0f;
            const float* bias = blist[wi];
            __half* out = olist[wi];
#pragma unroll
            for (int obk = 0; obk < 8; obk++) {
                int d = obk*8 + 2*(l&3);
                float b0 = bias[o0 + d], b1 = bias[o0 + d + 1];
                *(__half2*)&out[(nb_ + r0)*DKK + d] =
                    __floats2half2_rn((acc[obk][0]+b0)*scale, (acc[obk][1]+b1)*scale);
                *(__half2*)&out[(nb_ + r0 + 8)*DKK + d] =
                    __floats2half2_rn((acc[obk][2]+b0)*scale, (acc[obk][3]+b1)*scale);
            }
        }

        if (wi < 2) {
            __syncthreads();
            const __half* wn = wlist[wi+1];
#pragma unroll
            for (int t = 0; t < 4; t++) {
                int idx = tid + t*256;
                int r = idx >> 4, c = idx & 15;
                cp16(sb + PT_WS + r*528 + c*16, wn + (size_t)(o0 + r)*CC + c*8);
            }
            CP_COMMIT();
#pragma unroll
            for (int t = 0; t < 4; t++) {
                int idx = tid + t*256;
                int r = idx >> 4, c = idx & 15;
                cp16(sb + PT_WS + r*528 + 256 + c*16, wn + (size_t)(o0 + r)*CC + 128 + c*8);
            }
            CP_COMMIT();
        }
    }
}

// ---------------------------------------------------------------------------
// proj_o: out[o][n] = sum_c wp[o][c] * p[c][n] + bias + residual (f32 out)
// ---------------------------------------------------------------------------
__global__ __launch_bounds__(256,2) void proj_o_kernel(
    const __half* __restrict__ pg, const __half* __restrict__ wg,
    const float* __restrict__ bias, const float* __restrict__ res,
    float* __restrict__ out)
{
    extern __shared__ __align__(128) char sm[];
    const uint32_t sb = smem_u32(sm);
    const int tid = threadIdx.x, l = tid & 31;
    const int wo = (tid >> 5) & 3, wn = tid >> 7;
    const int n0 = blockIdx.x*128, o0 = blockIdx.y*64, b = blockIdx.z;
    const __half* pb = pg + (size_t)b*CC*NN;

#pragma unroll
    for (int t = 0; t < 8; t++) {
        int idx = tid + t*256;
        int r = idx >> 4, c = idx & 15;
        cp16(sb + r*272 + c*16, pb + (size_t)r*NN + n0 + c*8);
    }
#pragma unroll
    for (int t = 0; t < 4; t++) {
        int idx = tid + t*256;
        int r = idx >> 4, c = idx & 15;
        cp16(sb + PT_WS + r*528 + c*16, wg + (size_t)(o0 + r)*CC + c*8);
    }
    CP_COMMIT();
#pragma unroll
    for (int t = 0; t < 8; t++) {
        int idx = tid + t*256;
        int r = idx >> 4, c = idx & 15;
        cp16(sb + (128 + r)*272 + c*16, pb + (size_t)(128 + r)*NN + n0 + c*8);
    }
#pragma unroll
    for (int t = 0; t < 4; t++) {
        int idx = tid + t*256;
        int r = idx >> 4, c = idx & 15;
        cp16(sb + PT_WS + r*528 + 256 + c*16, wg + (size_t)(o0 + r)*CC + 128 + c*8);
    }
    CP_COMMIT();

    float acc[8][4];
#pragma unroll
    for (int i = 0; i < 8; i++)
#pragma unroll
        for (int j = 0; j < 4; j++) acc[i][j] = 0.0f;

    const int m = l >> 3;
    CP_WAIT1();
    __syncthreads();
#pragma unroll
    for (int half = 0; half < 2; half++) {
#pragma unroll
        for (int ks8 = 0; ks8 < 8; ks8++) {
            const int ks = half*8 + ks8;
            uint32_t af[4];
            ldmx4(af, sb + PT_WS + (uint32_t)(wo*16 + (l&15))*528
                          + (uint32_t)(ks*32 + (l>>4)*16));
#pragma unroll
            for (int nb2 = 0; nb2 < 4; nb2++) {
                uint32_t bf[4];
                ldmx4t(bf, sb + (uint32_t)(ks*16 + (m&1)*8 + (l&7))*272
                              + (uint32_t)(wn*64 + nb2*16 + (m>>1)*8)*2);
                mma_f16(acc[nb2*2+0], af, bf+0);
                mma_f16(acc[nb2*2+1], af, bf+2);
            }
        }
        if (half == 0) { CP_WAIT0(); __syncthreads(); }
    }

    const int or0 = o0 + wo*16 + (l>>2);
    const float b0 = bias[or0], b1 = bias[or0+8];
#pragma unroll
    for (int nb = 0; nb < 8; nb++) {
        int n = n0 + wn*64 + nb*8 + 2*(l&3);
        size_t i0 = ((size_t)(b*CC) + or0)*NN + n;
        size_t i1 = i0 + (size_t)8*NN;
        float2 r0v = *(const float2*)&res[i0];
        float2 r1v = *(const float2*)&res[i1];
        *(float2*)&out[i0] = make_float2(acc[nb][0]+b0+r0v.x, acc[nb][1]+b0+r0v.y);
        *(float2*)&out[i1] = make_float2(acc[nb][2]+b1+r1v.x, acc[nb][3]+b1+r1v.y);
    }
}

// ---------------------------------------------------------------------------
// FA2-style attention, fp16 mma.sync. 4 warps x 32 query rows, f16 S-accum
// (R14, validated). Q fragments from GMEM (R11 mechanism, validated) -> no Q
// smem -> 72KB -> 3 CTA/SM under __launch_bounds__(128,3); f16 S-accum freed
// the registers that made R11 spill.
// SMEM: K double[128x144B] + V double[128x144B].
// ---------------------------------------------------------------------------
#define OFF_K 0u
#define OFF_V 36864u
#define ST_KV 18432u
#define ATT_SMEM 73728u

__global__ __launch_bounds__(128,3) void attn_mma_kernel(
    const __half* __restrict__ qg, const __half* __restrict__ kg,
    const __half* __restrict__ vg, __half* __restrict__ og)
{
    extern __shared__ __align__(128) char sm[];
    const uint32_t sb = smem_u32(sm);
    const int tid = threadIdx.x;
    const int w = tid >> 5, l = tid & 31;
    const int qr0 = w * 32;
    const int gr  = l >> 2;
    const int n0 = blockIdx.x * 128;
    const int h = blockIdx.y, b = blockIdx.z;

    const size_t qkbase = (size_t)(b*HH + h) * NN * DKK;

    // stage0 K,V
#pragma unroll
    for (int t = 0; t < 8; t++) {
        int idx = tid + t*128;
        int r = idx >> 3, c = idx & 7;
        cp16(sb + OFF_K + r*144 + c*16, kg + qkbase + (size_t)r*DKK + c*8);
    }
#pragma unroll
    for (int t = 0; t < 8; t++) {
        int idx = tid + t*128;
        int r = idx >> 3, c = idx & 7;
        cp16(sb + OFF_V + r*144 + c*16, vg + qkbase + (size_t)r*DKK + c*8);
    }
    CP_COMMIT();

    // Q fragments straight from GMEM (m16n8k16 A-operand layout; R11-validated)
    uint32_t qf[2][4][4];
    {
        const __half* qp = qg + qkbase;
#pragma unroll
        for (int t2 = 0; t2 < 2; t2++) {
            const size_t r0 = (size_t)(n0 + qr0 + t2*16 + (l >> 2));
#pragma unroll
            for (int s = 0; s < 4; s++) {
                const int d0 = s*16 + 2*(l & 3);
                qf[t2][s][0] = *(const uint32_t*)&qp[r0*DKK + d0];
                qf[t2][s][1] = *(const uint32_t*)&qp[(r0 + 8)*DKK + d0];
                qf[t2][s][2] = *(const uint32_t*)&qp[r0*DKK + d0 + 8];
                qf[t2][s][3] = *(const uint32_t*)&qp[(r0 + 8)*DKK + d0 + 8];
            }
        }
    }

    float oacc[2][8][4];
#pragma unroll
    for (int t2 = 0; t2 < 2; t2++)
#pragma unroll
        for (int td = 0; td < 8; td++)
#pragma unroll
            for (int i = 0; i < 4; i++) oacc[t2][td][i] = 0.0f;
    float ls0[2] = {0.0f, 0.0f}, ls1[2] = {0.0f, 0.0f};

    for (int it = 0; it < 32; it++) {
        {
            int nkt = (it + 1 < 32) ? (it + 1) * 128 : 0;
            uint32_t kdst = sb + OFF_K + ((it + 1) & 1) * ST_KV;
            uint32_t vdst = sb + OFF_V + ((it + 1) & 1) * ST_KV;
#pragma unroll
            for (int t = 0; t < 8; t++) {
                int idx = tid + t*128;
                int r = idx >> 3, c = idx & 7;
                cp16(kdst + r*144 + c*16, kg + qkbase + (size_t)(nkt + r)*DKK + c*8);
            }
#pragma unroll
            for (int t = 0; t < 8; t++) {
                int idx = tid + t*128;
                int r = idx >> 3, c = idx & 7;
                cp16(vdst + r*144 + c*16, vg + qkbase + (size_t)(nkt + r)*DKK + c*8);
            }
            CP_COMMIT();
        }
        CP_WAIT1();
        __syncthreads();

        const uint32_t kbb = sb + OFF_K + (it & 1) * ST_KV;
        const uint32_t vbb = sb + OFF_V + (it & 1) * ST_KV;

        uint32_t lh[4] = {0u, 0u, 0u, 0u};
        uint32_t pk[2][8][2];

#pragma unroll
        for (int hf = 0; hf < 2; hf++) {
            // S = Q K^T in f16 accum, softmax fused per strip
#pragma unroll
            for (int t = 0; t < 8; t++) {
                uint32_t kf[8];
                uint32_t ra = kbb + (uint32_t)(hf*64 + t*8 + (l & 7))*144
                                  + (uint32_t)((l >> 3)*16);
                ldmx4(kf,   ra);
                ldmx4(kf+4, ra + 64);
                uint32_t s20[2] = {0u, 0u}, s21[2] = {0u, 0u};
#pragma unroll
                for (int s = 0; s < 4; s++) {
                    mma_f16h(s20, qf[0][s], kf + 2*s);
                    mma_f16h(s21, qf[1][s], kf + 2*s);
                }
                pk[0][t][0] = hx2(s20[0]);
                pk[0][t][1] = hx2(s20[1]);
                pk[1][t][0] = hx2(s21[0]);
                pk[1][t][1] = hx2(s21[1]);
                lh[0] = hadd2u(lh[0], pk[0][t][0]);
                lh[1] = hadd2u(lh[1], pk[0][t][1]);
                lh[2] = hadd2u(lh[2], pk[1][t][0]);
                lh[3] = hadd2u(lh[3], pk[1][t][1]);
            }

            // O += P V (V fragments shared across both row-tiles)
            const int mq = l >> 3;
#pragma unroll
            for (int td = 0; td < 8; td++) {
                uint32_t vf[8];
                uint32_t ra = vbb + (uint32_t)(hf*64 + mq*8 + (l & 7))*144
                                  + (uint32_t)(td*16);
                ldmx4t(vf,   ra);               // keys j 0..31
                ldmx4t(vf+4, ra + 32*144);      // keys j 32..63
#pragma unroll
                for (int t2 = 0; t2 < 2; t2++) {
                    uint32_t a0[4] = {pk[t2][0][0], pk[t2][0][1], pk[t2][1][0], pk[t2][1][1]};
                    uint32_t a1[4] = {pk[t2][2][0], pk[t2][2][1], pk[t2][3][0], pk[t2][3][1]};
                    uint32_t a2[4] = {pk[t2][4][0], pk[t2][4][1], pk[t2][5][0], pk[t2][5][1]};
                    uint32_t a3[4] = {pk[t2][6][0], pk[t2][6][1], pk[t2][7][0], pk[t2][7][1]};
                    mma_f16(oacc[t2][td], a0, vf + 0);
                    mma_f16(oacc[t2][td], a1, vf + 2);
                    mma_f16(oacc[t2][td], a2, vf + 4);
                    mma_f16(oacc[t2][td], a3, vf + 6);
                }
            }
        }

#pragma unroll
        for (int t2 = 0; t2 < 2; t2++) {
            float2 f0 = h2f2(lh[t2*2+0]);
            float2 f1 = h2f2(lh[t2*2+1]);
            ls0[t2] += f0.x + f0.y;
            ls1[t2] += f1.x + f1.y;
        }
        __syncthreads();
    }

#pragma unroll
    for (int t2 = 0; t2 < 2; t2++) {
        ls0[t2] += __shfl_xor_sync(0xFFFFFFFFu, ls0[t2], 1);
        ls0[t2] += __shfl_xor_sync(0xFFFFFFFFu, ls0[t2], 2);
        ls1[t2] += __shfl_xor_sync(0xFFFFFFFFu, ls1[t2], 1);
        ls1[t2] += __shfl_xor_sync(0xFFFFFFFFu, ls1[t2], 2);
    }

    const size_t obase = ((size_t)b*CC + h*DKK)*NN;
#pragma unroll
    for (int t2 = 0; t2 < 2; t2++) {
        const float inv0 = 1.0f / ls0[t2];
        const float inv1 = 1.0f / ls1[t2];
        const int row0 = n0 + qr0 + t2*16 + gr;
        const int row1 = row0 + 8;
#pragma unroll
        for (int td = 0; td < 8; td++) {
            int d = td*8 + (l & 3)*2;
            og[obase + (size_t)d*NN + row0]     = __float2half(oacc[t2][td][0]*inv0);
            og[obase + (size_t)(d+1)*NN + row0] = __float2half(oacc[t2][td][1]*inv0);
            og[obase + (size_t)d*NN + row1]     = __float2half(oacc[t2][td][2]*inv1);
            og[obase + (size_t)(d+1)*NN + row1] = __float2half(oacc[t2][td][3]*inv1);
        }
    }
}

// ---------------------------------------------------------------------------

extern "C" void kernel_launch(void* const* d_in, const int* in_sizes, int n_in,
                              void* d_out, int out_size)
{
    const float* x  = (const float*)d_in[0];
    const float* wq = (const float*)d_in[1];
    const float* bq = (const float*)d_in[2];
    const float* wk = (const float*)d_in[3];
    const float* bk = (const float*)d_in[4];
    const float* wv = (const float*)d_in[5];
    const float* bv = (const float*)d_in[6];
    const float* wp = (const float*)d_in[7];
    const float* bp = (const float*)d_in[8];
    float* out = (float*)d_out;

    __half *xh, *wqh, *wkh, *wvh, *wph, *qh, *kh, *vh, *ah;
    cudaGetSymbolAddress((void**)&xh,  g_xh);
    cudaGetSymbolAddress((void**)&wqh, g_wq);
    cudaGetSymbolAddress((void**)&wkh, g_wk);
    cudaGetSymbolAddress((void**)&wvh, g_wv);
    cudaGetSymbolAddress((void**)&wph, g_wp);
    cudaGetSymbolAddress((void**)&qh,  g_qh);
    cudaGetSymbolAddress((void**)&kh,  g_kh);
    cudaGetSymbolAddress((void**)&vh,  g_vh);
    cudaGetSymbolAddress((void**)&ah,  g_ah);

    cudaFuncSetAttribute(attn_mma_kernel,
                         cudaFuncAttributeMaxDynamicSharedMemorySize, ATT_SMEM);
    cudaFuncSetAttribute(proj_qkv_kernel,
                         cudaFuncAttributeMaxDynamicSharedMemorySize, PT_SMEM);
    cudaFuncSetAttribute(proj_o_kernel,
                         cudaFuncAttributeMaxDynamicSharedMemorySize, PT_SMEM);

    // f16 conversion pre-pass
    const int xn4 = BB*CC*NN/4;
    cvt_kernel<<<xn4/256, 256>>>((const float4*)x, xh, xn4);
    const int wn4 = CC*CC/4;
    dim3 wg(wn4/256, 4);
    cvt_w4_kernel<<<wg, 256>>>((const float4*)wq, (const float4*)wk,
                               (const float4*)wv, (const float4*)wp,
                               wqh, wkh, wvh, wph, wn4);

    dim3 pg(NN/128, HH, BB);
    proj_qkv_kernel<<<pg, 256, PT_SMEM>>>(xh, wqh, wkh, wvh, bq, bk, bv,
                                          qh, kh, vh);

    dim3 ag(NN/128, HH, BB);
    attn_mma_kernel<<<ag, 128, ATT_SMEM>>>(qh, kh, vh, ah);

    dim3 og_(NN/128, CC/64, BB);
    proj_o_kernel<<<og_, 256, PT_SMEM>>>(ah, wph, bp, x, out);
}

// round 17
// speedup vs baseline: 1.0893x; 1.0893x over previous
#include <cuda_runtime.h>
#include <cuda_fp16.h>
#include <cstdint>

#define BB 4
#define CC 256
#define NN 4096
#define HH 4
#define DKK 64

// scratch (allocation-free rule: __device__ globals)
__device__ __half g_xh[(size_t)BB*CC*NN];       // x in f16 [b,c,n]
__device__ __half g_wq[CC*CC], g_wk[CC*CC], g_wv[CC*CC], g_wp[CC*CC];
__device__ __half g_qh[(size_t)BB*HH*NN*DKK];   // [b,h,n,d] (pre-scaled)
__device__ __half g_kh[(size_t)BB*HH*NN*DKK];   // [b,h,n,d]
__device__ __half g_vh[(size_t)BB*HH*NN*DKK];   // [b,h,n,d]
__device__ __half g_ah[(size_t)BB*NN*CC];       // attn out [b,n,c] (c contiguous)

// Q pre-scale: (1/sqrt(64)) * log2(e), folded into the Q projection
#define QSCALE 0.1803368801111204f

// ---------------------------------------------------------------------------
// helpers
// ---------------------------------------------------------------------------
__device__ __forceinline__ uint32_t smem_u32(const void* p){
    uint32_t a;
    asm("{ .reg .u64 t; cvta.to.shared.u64 t, %1; cvt.u32.u64 %0, t; }":"=r"(a):"l"(p));
    return a;
}
__device__ __forceinline__ void cp16(uint32_t dst, const void* src){
    asm volatile("cp.async.cg.shared.global [%0],[%1],16;"::"r"(dst),"l"(src):"memory");
}
#define CP_COMMIT() asm volatile("cp.async.commit_group;":::"memory")
#define CP_WAIT0()  asm volatile("cp.async.wait_group 0;":::"memory")
#define CP_WAIT1()  asm volatile("cp.async.wait_group 1;":::"memory")

__device__ __forceinline__ void ldmx4(uint32_t* r, uint32_t addr){
    asm volatile("ldmatrix.sync.aligned.m8n8.x4.shared.b16 {%0,%1,%2,%3}, [%4];"
        : "=r"(r[0]),"=r"(r[1]),"=r"(r[2]),"=r"(r[3]) : "r"(addr));
}
__device__ __forceinline__ void ldmx4t(uint32_t* r, uint32_t addr){
    asm volatile("ldmatrix.sync.aligned.m8n8.x4.trans.shared.b16 {%0,%1,%2,%3}, [%4];"
        : "=r"(r[0]),"=r"(r[1]),"=r"(r[2]),"=r"(r[3]) : "r"(addr));
}
__device__ __forceinline__ void mma_f16(float* c, const uint32_t* a, const uint32_t* b){
    asm volatile("mma.sync.aligned.m16n8k16.row.col.f32.f16.f16.f32 "
        "{%0,%1,%2,%3}, {%4,%5,%6,%7}, {%8,%9}, {%0,%1,%2,%3};"
        : "+f"(c[0]),"+f"(c[1]),"+f"(c[2]),"+f"(c[3])
        : "r"(a[0]),"r"(a[1]),"r"(a[2]),"r"(a[3]), "r"(b[0]),"r"(b[1]));
}
// f16-accumulate variant: C/D are 2 regs of f16x2
__device__ __forceinline__ void mma_f16h(uint32_t* c, const uint32_t* a, const uint32_t* b){
    asm volatile("mma.sync.aligned.m16n8k16.row.col.f16.f16.f16.f16 "
        "{%0,%1}, {%2,%3,%4,%5}, {%6,%7}, {%0,%1};"
        : "+r"(c[0]),"+r"(c[1])
        : "r"(a[0]),"r"(a[1]),"r"(a[2]),"r"(a[3]), "r"(b[0]),"r"(b[1]));
}
__device__ __forceinline__ uint32_t hx2(uint32_t x){
    uint32_t r; asm("ex2.approx.f16x2 %0, %1;" : "=r"(r) : "r"(x)); return r;
}
__device__ __forceinline__ uint32_t hadd2u(uint32_t a, uint32_t b){
    uint32_t r; asm("add.rn.f16x2 %0, %1, %2;" : "=r"(r) : "r"(a), "r"(b)); return r;
}
__device__ __forceinline__ float2 h2f2(uint32_t u){
    __half2 h = *reinterpret_cast<__half2*>(&u);
    return __half22float2(h);
}

// ---------------------------------------------------------------------------
// f32 -> f16 conversion pre-pass
// ---------------------------------------------------------------------------
__global__ __launch_bounds__(256) void cvt_kernel(
    const float4* __restrict__ src, __half* __restrict__ dst, int n4)
{
    int i = blockIdx.x*blockDim.x + threadIdx.x;
    if (i < n4) {
        float4 v = src[i];
        __half2* d2 = (__half2*)(dst + (size_t)i*4);
        d2[0] = __floats2half2_rn(v.x, v.y);
        d2[1] = __floats2half2_rn(v.z, v.w);
    }
}
__global__ __launch_bounds__(256) void cvt_w4_kernel(
    const float4* __restrict__ w0, const float4* __restrict__ w1,
    const float4* __restrict__ w2, const float4* __restrict__ w3,
    __half* __restrict__ d0, __half* __restrict__ d1,
    __half* __restrict__ d2, __half* __restrict__ d3, int n4)
{
    const float4* s; __half* d;
    switch (blockIdx.y) {
        case 0: s = w0; d = d0; break;
        case 1: s = w1; d = d1; break;
        case 2: s = w2; d = d2; break;
        default: s = w3; d = d3; break;
    }
    int i = blockIdx.x*blockDim.x + threadIdx.x;
    if (i < n4) {
        float4 v = s[i];
        __half2* dd = (__half2*)(d + (size_t)i*4);
        dd[0] = __floats2half2_rn(v.x, v.y);
        dd[1] = __floats2half2_rn(v.z, v.w);
    }
}

// ---------------------------------------------------------------------------
// proj_qkv: one CTA loads its x tile ONCE and computes q,k,v for its head.
// out f16 [b][h][n][64]. CTA = 128 n x 64 o. K=256, w staged in 2 halves.
// ---------------------------------------------------------------------------
#define PT_WS   69632u
#define PT_SMEM 103424u

__global__ __launch_bounds__(256,2) void proj_qkv_kernel(
    const __half* __restrict__ xg,
    const __half* __restrict__ wq, const __half* __restrict__ wk,
    const __half* __restrict__ wv,
    const float* __restrict__ bq, const float* __restrict__ bk,
    const float* __restrict__ bv,
    __half* __restrict__ qo, __half* __restrict__ ko, __half* __restrict__ vo)
{
    extern __shared__ __align__(128) char sm[];
    const uint32_t sb = smem_u32(sm);
    const int tid = threadIdx.x, l = tid & 31, w = tid >> 5;
    const int n0 = blockIdx.x*128, h = blockIdx.y, b = blockIdx.z;
    const int o0 = h*64;
    const __half* xb = xg + (size_t)b*CC*NN;

    const __half* wlist[3] = {wq, wk, wv};
    const float*  blist[3] = {bq, bk, bv};
    __half*       olist[3] = {qo, ko, vo};

#pragma unroll
    for (int t = 0; t < 8; t++) {
        int idx = tid + t*256;
        int r = idx >> 4, c = idx & 15;
        cp16(sb + r*272 + c*16, xb + (size_t)r*NN + n0 + c*8);
    }
#pragma unroll
    for (int t = 0; t < 4; t++) {
        int idx = tid + t*256;
        int r = idx >> 4, c = idx & 15;
        cp16(sb + PT_WS + r*528 + c*16, wq + (size_t)(o0 + r)*CC + c*8);
    }
    CP_COMMIT();
#pragma unroll
    for (int t = 0; t < 8; t++) {
        int idx = tid + t*256;
        int r = idx >> 4, c = idx & 15;
        cp16(sb + (128 + r)*272 + c*16, xb + (size_t)(128 + r)*NN + n0 + c*8);
    }
#pragma unroll
    for (int t = 0; t < 4; t++) {
        int idx = tid + t*256;
        int r = idx >> 4, c = idx & 15;
        cp16(sb + PT_WS + r*528 + 256 + c*16, wq + (size_t)(o0 + r)*CC + 128 + c*8);
    }
    CP_COMMIT();

    const int m = l >> 3;
    const int r0 = n0 + w*16 + (l>>2);
    const size_t nb_ = (size_t)(b*HH + h)*NN;

    for (int wi = 0; wi < 3; wi++) {
        float acc[8][4];
#pragma unroll
        for (int i = 0; i < 8; i++)
#pragma unroll
            for (int j = 0; j < 4; j++) acc[i][j] = 0.0f;

        CP_WAIT1();
        __syncthreads();
#pragma unroll
        for (int half = 0; half < 2; half++) {
#pragma unroll
            for (int ks8 = 0; ks8 < 8; ks8++) {
                const int ks = half*8 + ks8;
                uint32_t af[4];
                ldmx4t(af, sb + (uint32_t)(ks*16 + (m>>1)*8 + (l&7))*272
                              + (uint32_t)(w*16 + (m&1)*8)*2);
#pragma unroll
                for (int ob2 = 0; ob2 < 4; ob2++) {
                    uint32_t bf[4];
                    ldmx4(bf, sb + PT_WS + (uint32_t)(ob2*16 + (m>>1)*8 + (l&7))*528
                                  + (uint32_t)(ks*16 + (m&1)*8)*2);
                    mma_f16(acc[ob2*2+0], af, bf+0);
                    mma_f16(acc[ob2*2+1], af, bf+2);
                }
            }
            if (half == 0) { CP_WAIT0(); __syncthreads(); }
        }

        {
            const float scale = (wi == 0) ? QSCALE : 1.0f;
            const float* bias = blist[wi];
            __half* out = olist[wi];
#pragma unroll
            for (int obk = 0; obk < 8; obk++) {
                int d = obk*8 + 2*(l&3);
                float b0 = bias[o0 + d], b1 = bias[o0 + d + 1];
                *(__half2*)&out[(nb_ + r0)*DKK + d] =
                    __floats2half2_rn((acc[obk][0]+b0)*scale, (acc[obk][1]+b1)*scale);
                *(__half2*)&out[(nb_ + r0 + 8)*DKK + d] =
                    __floats2half2_rn((acc[obk][2]+b0)*scale, (acc[obk][3]+b1)*scale);
            }
        }

        if (wi < 2) {
            __syncthreads();
            const __half* wn = wlist[wi+1];
#pragma unroll
            for (int t = 0; t < 4; t++) {
                int idx = tid + t*256;
                int r = idx >> 4, c = idx & 15;
                cp16(sb + PT_WS + r*528 + c*16, wn + (size_t)(o0 + r)*CC + c*8);
            }
            CP_COMMIT();
#pragma unroll
            for (int t = 0; t < 4; t++) {
                int idx = tid + t*256;
                int r = idx >> 4, c = idx & 15;
                cp16(sb + PT_WS + r*528 + 256 + c*16, wn + (size_t)(o0 + r)*CC + 128 + c*8);
            }
            CP_COMMIT();
        }
    }
}

// ---------------------------------------------------------------------------
// proj_o: out[o][n] = sum_c wp[o][c] * p[n][c] + bias + residual (f32 out)
// p is [b][n][256] (c contiguous) -> B operand via NON-trans ldmatrix.
// smem: p [128 n][256 c] pitch 528B + w [64 o][256 c] pitch 528B.
// ---------------------------------------------------------------------------
__global__ __launch_bounds__(256,2) void proj_o_kernel(
    const __half* __restrict__ pg, const __half* __restrict__ wg,
    const float* __restrict__ bias, const float* __restrict__ res,
    float* __restrict__ out)
{
    extern __shared__ __align__(128) char sm[];
    const uint32_t sb = smem_u32(sm);
    const int tid = threadIdx.x, l = tid & 31;
    const int wo = (tid >> 5) & 3, wn = tid >> 7;
    const int n0 = blockIdx.x*128, o0 = blockIdx.y*64, b = blockIdx.z;
    const __half* pb = pg + (size_t)b*NN*CC;

    // p tile: 128 rows x 512B (32 cp16 per row)
#pragma unroll
    for (int t = 0; t < 16; t++) {
        int idx = tid + t*256;
        int r = idx >> 5, c = idx & 31;
        cp16(sb + r*528 + c*16, pb + (size_t)(n0 + r)*CC + c*8);
    }
    // w tile: 64 rows x 512B
#pragma unroll
    for (int t = 0; t < 8; t++) {
        int idx = tid + t*256;
        int r = idx >> 5, c = idx & 31;
        cp16(sb + PT_WS + r*528 + c*16, wg + (size_t)(o0 + r)*CC + c*8);
    }
    CP_COMMIT(); CP_WAIT0();
    __syncthreads();

    float acc[8][4];
#pragma unroll
    for (int i = 0; i < 8; i++)
#pragma unroll
        for (int j = 0; j < 4; j++) acc[i][j] = 0.0f;

#pragma unroll
    for (int ks2 = 0; ks2 < 8; ks2++) {      // 8 chunks of 32 c
        uint32_t af0[4], af1[4];
        uint32_t aa = sb + PT_WS + (uint32_t)(wo*16 + (l&15))*528
                         + (uint32_t)(ks2*64 + (l>>4)*16);
        ldmx4(af0, aa);          // A: wp rows o, c k0-15 of chunk
        ldmx4(af1, aa + 32);     // A: c k16-31 of chunk
#pragma unroll
        for (int ns = 0; ns < 8; ns++) {
            uint32_t bf[4];
            ldmx4(bf, sb + (uint32_t)(wn*64 + ns*8 + (l&7))*528
                         + (uint32_t)(ks2*64 + (l>>3)*16));
            mma_f16(acc[ns], af0, bf + 0);
            mma_f16(acc[ns], af1, bf + 2);
        }
    }

    const int or0 = o0 + wo*16 + (l>>2);
    const float b0 = bias[or0], b1 = bias[or0+8];
#pragma unroll
    for (int ns = 0; ns < 8; ns++) {
        int n = n0 + wn*64 + ns*8 + 2*(l&3);
        size_t i0 = ((size_t)(b*CC) + or0)*NN + n;
        size_t i1 = i0 + (size_t)8*NN;
        float2 r0v = *(const float2*)&res[i0];
        float2 r1v = *(const float2*)&res[i1];
        *(float2*)&out[i0] = make_float2(acc[ns][0]+b0+r0v.x, acc[ns][1]+b0+r0v.y);
        *(float2*)&out[i1] = make_float2(acc[ns][2]+b1+r1v.x, acc[ns][3]+b1+r1v.y);
    }
}

// ---------------------------------------------------------------------------
// FA2-style attention, fp16 mma.sync. R14 config (best measured): 4 warps x
// 32 query rows, Q in smem, f16 S-accum, 2 CTA/SM. NEW: epilogue writes
// [b][n][256] (c contiguous) -> coalesced half2 stores.
// SMEM: Q[128x144B], K double[128x144B], V double[128x144B]. 90 KB.
// ---------------------------------------------------------------------------
#define OFF_Q 0u
#define OFF_K 18432u
#define OFF_V 55296u
#define ST_KV 18432u
#define ATT_SMEM 92160u

__global__ __launch_bounds__(128,2) void attn_mma_kernel(
    const __half* __restrict__ qg, const __half* __restrict__ kg,
    const __half* __restrict__ vg, __half* __restrict__ og)
{
    extern __shared__ __align__(128) char sm[];
    const uint32_t sb = smem_u32(sm);
    const int tid = threadIdx.x;
    const int w = tid >> 5, l = tid & 31;
    const int qr0 = w * 32;
    const int gr  = l >> 2;
    const int n0 = blockIdx.x * 128;
    const int h = blockIdx.y, b = blockIdx.z;

    const size_t qkbase = (size_t)(b*HH + h) * NN * DKK;

    // prologue: Q + stage0 (K,V)
#pragma unroll
    for (int t = 0; t < 8; t++) {
        int idx = tid + t*128;
        int r = idx >> 3, c = idx & 7;
        cp16(sb + OFF_Q + r*144 + c*16, qg + qkbase + (size_t)(n0 + r)*DKK + c*8);
    }
#pragma unroll
    for (int t = 0; t < 8; t++) {
        int idx = tid + t*128;
        int r = idx >> 3, c = idx & 7;
        cp16(sb + OFF_K + r*144 + c*16, kg + qkbase + (size_t)r*DKK + c*8);
    }
#pragma unroll
    for (int t = 0; t < 8; t++) {
        int idx = tid + t*128;
        int r = idx >> 3, c = idx & 7;
        cp16(sb + OFF_V + r*144 + c*16, vg + qkbase + (size_t)r*DKK + c*8);
    }
    CP_COMMIT();

    float oacc[2][8][4];
#pragma unroll
    for (int t2 = 0; t2 < 2; t2++)
#pragma unroll
        for (int td = 0; td < 8; td++)
#pragma unroll
            for (int i = 0; i < 4; i++) oacc[t2][td][i] = 0.0f;
    float ls0[2] = {0.0f, 0.0f}, ls1[2] = {0.0f, 0.0f};
    uint32_t qf[2][4][4];

    for (int it = 0; it < 32; it++) {
        {
            int nkt = (it + 1 < 32) ? (it + 1) * 128 : 0;
            uint32_t kdst = sb + OFF_K + ((it + 1) & 1) * ST_KV;
            uint32_t vdst = sb + OFF_V + ((it + 1) & 1) * ST_KV;
#pragma unroll
            for (int t = 0; t < 8; t++) {
                int idx = tid + t*128;
                int r = idx >> 3, c = idx & 7;
                cp16(kdst + r*144 + c*16, kg + qkbase + (size_t)(nkt + r)*DKK + c*8);
            }
#pragma unroll
            for (int t = 0; t < 8; t++) {
                int idx = tid + t*128;
                int r = idx >> 3, c = idx & 7;
                cp16(vdst + r*144 + c*16, vg + qkbase + (size_t)(nkt + r)*DKK + c*8);
            }
            CP_COMMIT();
        }
        CP_WAIT1();
        __syncthreads();

        if (it == 0) {
#pragma unroll
            for (int t2 = 0; t2 < 2; t2++)
#pragma unroll
                for (int s = 0; s < 4; s++)
                    ldmx4(qf[t2][s],
                          sb + OFF_Q + (uint32_t)(qr0 + t2*16 + (l & 15))*144
                                     + (uint32_t)((l >> 4)*16 + s*32));
        }

        const uint32_t kbb = sb + OFF_K + (it & 1) * ST_KV;
        const uint32_t vbb = sb + OFF_V + (it & 1) * ST_KV;

        uint32_t lh[4] = {0u, 0u, 0u, 0u};
        uint32_t pk[2][8][2];

#pragma unroll
        for (int hf = 0; hf < 2; hf++) {
            // S = Q K^T in f16 accum, softmax fused per strip
#pragma unroll
            for (int t = 0; t < 8; t++) {
                uint32_t kf[8];
                uint32_t ra = kbb + (uint32_t)(hf*64 + t*8 + (l & 7))*144
                                  + (uint32_t)((l >> 3)*16);
                ldmx4(kf,   ra);
                ldmx4(kf+4, ra + 64);
                uint32_t s20[2] = {0u, 0u}, s21[2] = {0u, 0u};
#pragma unroll
                for (int s = 0; s < 4; s++) {
                    mma_f16h(s20, qf[0][s], kf + 2*s);
                    mma_f16h(s21, qf[1][s], kf + 2*s);
                }
                pk[0][t][0] = hx2(s20[0]);
                pk[0][t][1] = hx2(s20[1]);
                pk[1][t][0] = hx2(s21[0]);
                pk[1][t][1] = hx2(s21[1]);
                lh[0] = hadd2u(lh[0], pk[0][t][0]);
                lh[1] = hadd2u(lh[1], pk[0][t][1]);
                lh[2] = hadd2u(lh[2], pk[1][t][0]);
                lh[3] = hadd2u(lh[3], pk[1][t][1]);
            }

            // O += P V (V fragments shared across both row-tiles)
            const int mq = l >> 3;
#pragma unroll
            for (int td = 0; td < 8; td++) {
                uint32_t vf[8];
                uint32_t ra = vbb + (uint32_t)(hf*64 + mq*8 + (l & 7))*144
                                  + (uint32_t)(td*16);
                ldmx4t(vf,   ra);               // keys j 0..31
                ldmx4t(vf+4, ra + 32*144);      // keys j 32..63
#pragma unroll
                for (int t2 = 0; t2 < 2; t2++) {
                    uint32_t a0[4] = {pk[t2][0][0], pk[t2][0][1], pk[t2][1][0], pk[t2][1][1]};
                    uint32_t a1[4] = {pk[t2][2][0], pk[t2][2][1], pk[t2][3][0], pk[t2][3][1]};
                    uint32_t a2[4] = {pk[t2][4][0], pk[t2][4][1], pk[t2][5][0], pk[t2][5][1]};
                    uint32_t a3[4] = {pk[t2][6][0], pk[t2][6][1], pk[t2][7][0], pk[t2][7][1]};
                    mma_f16(oacc[t2][td], a0, vf + 0);
                    mma_f16(oacc[t2][td], a1, vf + 2);
                    mma_f16(oacc[t2][td], a2, vf + 4);
                    mma_f16(oacc[t2][td], a3, vf + 6);
                }
            }
        }

#pragma unroll
        for (int t2 = 0; t2 < 2; t2++) {
            float2 f0 = h2f2(lh[t2*2+0]);
            float2 f1 = h2f2(lh[t2*2+1]);
            ls0[t2] += f0.x + f0.y;
            ls1[t2] += f1.x + f1.y;
        }
        __syncthreads();
    }

#pragma unroll
    for (int t2 = 0; t2 < 2; t2++) {
        ls0[t2] += __shfl_xor_sync(0xFFFFFFFFu, ls0[t2], 1);
        ls0[t2] += __shfl_xor_sync(0xFFFFFFFFu, ls0[t2], 2);
        ls1[t2] += __shfl_xor_sync(0xFFFFFFFFu, ls1[t2], 1);
        ls1[t2] += __shfl_xor_sync(0xFFFFFFFFu, ls1[t2], 2);
    }

    // epilogue: coalesced half2 stores into [b][n][256]
    const size_t ob2 = (size_t)b * NN;
    const int c0 = h*DKK;
#pragma unroll
    for (int t2 = 0; t2 < 2; t2++) {
        const float inv0 = 1.0f / ls0[t2];
        const float inv1 = 1.0f / ls1[t2];
        const int row0 = n0 + qr0 + t2*16 + gr;
        const int row1 = row0 + 8;
#pragma unroll
        for (int td = 0; td < 8; td++) {
            int d = td*8 + (l & 3)*2;
            *(__half2*)&og[(ob2 + row0)*CC + c0 + d] =
                __floats2half2_rn(oacc[t2][td][0]*inv0, oacc[t2][td][1]*inv0);
            *(__half2*)&og[(ob2 + row1)*CC + c0 + d] =
                __floats2half2_rn(oacc[t2][td][2]*inv1, oacc[t2][td][3]*inv1);
        }
    }
}

// ---------------------------------------------------------------------------

extern "C" void kernel_launch(void* const* d_in, const int* in_sizes, int n_in,
                              void* d_out, int out_size)
{
    const float* x  = (const float*)d_in[0];
    const float* wq = (const float*)d_in[1];
    const float* bq = (const float*)d_in[2];
    const float* wk = (const float*)d_in[3];
    const float* bk = (const float*)d_in[4];
    const float* wv = (const float*)d_in[5];
    const float* bv = (const float*)d_in[6];
    const float* wp = (const float*)d_in[7];
    const float* bp = (const float*)d_in[8];
    float* out = (float*)d_out;

    __half *xh, *wqh, *wkh, *wvh, *wph, *qh, *kh, *vh, *ah;
    cudaGetSymbolAddress((void**)&xh,  g_xh);
    cudaGetSymbolAddress((void**)&wqh, g_wq);
    cudaGetSymbolAddress((void**)&wkh, g_wk);
    cudaGetSymbolAddress((void**)&wvh, g_wv);
    cudaGetSymbolAddress((void**)&wph, g_wp);
    cudaGetSymbolAddress((void**)&qh,  g_qh);
    cudaGetSymbolAddress((void**)&kh,  g_kh);
    cudaGetSymbolAddress((void**)&vh,  g_vh);
    cudaGetSymbolAddress((void**)&ah,  g_ah);

    cudaFuncSetAttribute(attn_mma_kernel,
                         cudaFuncAttributeMaxDynamicSharedMemorySize, ATT_SMEM);
    cudaFuncSetAttribute(proj_qkv_kernel,
                         cudaFuncAttributeMaxDynamicSharedMemorySize, PT_SMEM);
    cudaFuncSetAttribute(proj_o_kernel,
                         cudaFuncAttributeMaxDynamicSharedMemorySize, PT_SMEM);

    // f16 conversion pre-pass
    const int xn4 = BB*CC*NN/4;
    cvt_kernel<<<xn4/256, 256>>>((const float4*)x, xh, xn4);
    const int wn4 = CC*CC/4;
    dim3 wg(wn4/256, 4);
    cvt_w4_kernel<<<wg, 256>>>((const float4*)wq, (const float4*)wk,
                               (const float4*)wv, (const float4*)wp,
                               wqh, wkh, wvh, wph, wn4);

    dim3 pg(NN/128, HH, BB);
    proj_qkv_kernel<<<pg, 256, PT_SMEM>>>(xh, wqh, wkh, wvh, bq, bk, bv,
                                          qh, kh, vh);

    dim3 ag(NN/128, HH, BB);
    attn_mma_kernel<<<ag, 128, ATT_SMEM>>>(qh, kh, vh, ah);

    dim3 og_(NN/128, CC/64, BB);
    proj_o_kernel<<<og_, 256, PT_SMEM>>>(ah, wph, bp, x, out);
}